// round 6
// baseline (speedup 1.0000x reference)
#include <cuda_runtime.h>
#include <math.h>

// Problem constants
#define BB 512          // batch
#define DD 512          // feature dim (K)
#define CC 100000       // classes
#define SCALE 64.0f

// GEMM tiling
#define MBT 128         // batch tile
#define NBT 64          // class tile
#define KCT 16          // K chunk
#define NKCH (DD / KCT) // 32 chunks

// ---------------- scratch (device globals; no allocations allowed) ----------
__device__ float g_xn[BB * DD];     // normalized x, row-major [m][k]
__device__ float g_xnT[DD * BB];    // normalized x, transposed [k][m]
__device__ float g_wscale[CC];      // 64 / max(||w_c||, eps)
__device__ float g_expsum[BB];      // per-row sum of exp(L - 64)
__device__ float g_nll[BB];         // per-row nll
__device__ int   g_is64;            // label dtype flag (1 = int64)

// ---------------- label dtype probe ----------------------------------------
// If labels are int64 (little-endian), every odd int32 word (high half of a
// label < 2^31) is zero. If int32, odd words are actual labels (nonzero with
// overwhelming probability for 256 random draws in [0,1e5)).
__global__ void k_probe(const int* __restrict__ lab)
{
    __shared__ int s_any;
    if (threadIdx.x == 0) s_any = 0;
    __syncthreads();
    int idx = 2 * threadIdx.x + 1;           // 1..511 (safe for both widths)
    if (lab[idx] != 0) atomicOr(&s_any, 1);
    __syncthreads();
    if (threadIdx.x == 0) g_is64 = (s_any == 0) ? 1 : 0;
}

// ---------------- x row-normalize (+ zero expsum each launch) ---------------
__global__ void k_norm_x(const float* __restrict__ x)
{
    __shared__ float s_part[4];
    __shared__ float s_inv;
    const int m = blockIdx.x;
    const int t = threadIdx.x;                 // 128 threads, 1 float4 each
    float4 v = ((const float4*)x)[m * 128 + t];
    float ss = v.x * v.x + v.y * v.y + v.z * v.z + v.w * v.w;
    #pragma unroll
    for (int o = 16; o > 0; o >>= 1) ss += __shfl_xor_sync(0xffffffffu, ss, o);
    if ((t & 31) == 0) s_part[t >> 5] = ss;
    __syncthreads();
    if (t == 0) {
        float tot = s_part[0] + s_part[1] + s_part[2] + s_part[3];
        s_inv = 1.0f / fmaxf(sqrtf(tot), 1e-12f);
        g_expsum[m] = 0.0f;                    // re-zeroed every graph replay
    }
    __syncthreads();
    const float inv = s_inv;
    float4 o4 = make_float4(v.x * inv, v.y * inv, v.z * inv, v.w * inv);
    ((float4*)g_xn)[m * 128 + t] = o4;
    const int k = t * 4;
    g_xnT[(k + 0) * BB + m] = o4.x;
    g_xnT[(k + 1) * BB + m] = o4.y;
    g_xnT[(k + 2) * BB + m] = o4.z;
    g_xnT[(k + 3) * BB + m] = o4.w;
}

// ---------------- W row norms (one warp per class row) ----------------------
__global__ void k_norm_w(const float* __restrict__ w)
{
    const int c = blockIdx.x * 8 + (threadIdx.x >> 5);
    const int lane = threadIdx.x & 31;
    if (c >= CC) return;
    const float4* w4 = (const float4*)(w + (size_t)c * DD);
    float ss = 0.0f;
    #pragma unroll
    for (int q = 0; q < 4; q++) {
        float4 v = w4[q * 32 + lane];
        ss += v.x * v.x + v.y * v.y + v.z * v.z + v.w * v.w;
    }
    #pragma unroll
    for (int o = 16; o > 0; o >>= 1) ss += __shfl_xor_sync(0xffffffffu, ss, o);
    if (lane == 0) g_wscale[c] = SCALE / fmaxf(sqrtf(ss), 1e-12f);
}

// ---------------- main GEMM + fused exp/Sigma epilogue ----------------------
// Block tile: [128 batch x 64 classes]; 256 threads, reg tile 8x4.
// Double-buffered smem with register prefetch of the next K chunk.
__global__ __launch_bounds__(256, 2) void k_gemm(const float* __restrict__ w)
{
    __shared__ __align__(16) float As[2][KCT][MBT];      // [k][m]
    __shared__ __align__(16) float Bs[2][KCT][68];       // [k][c], padded

    const int tid = threadIdx.x;
    const int tx = tid & 15;        // class direction (x4)
    const int ty = tid >> 4;        // batch direction (x8)
    const int cBase = blockIdx.x * NBT;
    const int mBase = blockIdx.y * MBT;

    // A global->smem mapping: 16 k-rows x 16 threads x 8 m each
    const int a_kk = tid >> 4;
    const int a_mq = tid & 15;
    const float* asrc = g_xnT + a_kk * BB + mBase + a_mq * 8;

    // B global->smem mapping (transpose on the fly): 64 classes x 4 k-quads
    const int b_cc = tid >> 2;
    const int b_kq = tid & 3;
    const int b_c = cBase + b_cc;
    const bool b_ok = (b_c < CC);
    const float* bsrc = w + (size_t)(b_ok ? b_c : 0) * DD + b_kq * 4;

    float acc[8][4];
    #pragma unroll
    for (int i = 0; i < 8; i++)
        #pragma unroll
        for (int j = 0; j < 4; j++) acc[i][j] = 0.0f;

    // Prologue: fetch + stage chunk 0
    float4 pa0 = *(const float4*)(asrc);
    float4 pa1 = *(const float4*)(asrc + 4);
    float4 pb = b_ok ? *(const float4*)(bsrc) : make_float4(0, 0, 0, 0);
    *(float4*)&As[0][a_kk][a_mq * 8]     = pa0;
    *(float4*)&As[0][a_kk][a_mq * 8 + 4] = pa1;
    Bs[0][b_kq * 4 + 0][b_cc] = pb.x;
    Bs[0][b_kq * 4 + 1][b_cc] = pb.y;
    Bs[0][b_kq * 4 + 2][b_cc] = pb.z;
    Bs[0][b_kq * 4 + 3][b_cc] = pb.w;
    __syncthreads();

    for (int kc = 0; kc < NKCH; kc++) {
        const int cur = kc & 1;
        if (kc + 1 < NKCH) {                        // prefetch next chunk
            const int k0 = (kc + 1) * KCT;
            pa0 = *(const float4*)(asrc + k0 * BB);
            pa1 = *(const float4*)(asrc + k0 * BB + 4);
            pb = b_ok ? *(const float4*)(bsrc + k0) : make_float4(0, 0, 0, 0);
        }
        #pragma unroll
        for (int k = 0; k < KCT; k++) {
            float4 a0 = *(const float4*)&As[cur][k][ty * 8];
            float4 a1 = *(const float4*)&As[cur][k][ty * 8 + 4];
            float4 b4 = *(const float4*)&Bs[cur][k][tx * 4];
            float av[8] = {a0.x, a0.y, a0.z, a0.w, a1.x, a1.y, a1.z, a1.w};
            float bv[4] = {b4.x, b4.y, b4.z, b4.w};
            #pragma unroll
            for (int i = 0; i < 8; i++)
                #pragma unroll
                for (int j = 0; j < 4; j++)
                    acc[i][j] = fmaf(av[i], bv[j], acc[i][j]);
        }
        if (kc + 1 < NKCH) {                        // stage into other buffer
            const int nxt = cur ^ 1;
            *(float4*)&As[nxt][a_kk][a_mq * 8]     = pa0;
            *(float4*)&As[nxt][a_kk][a_mq * 8 + 4] = pa1;
            Bs[nxt][b_kq * 4 + 0][b_cc] = pb.x;
            Bs[nxt][b_kq * 4 + 1][b_cc] = pb.y;
            Bs[nxt][b_kq * 4 + 2][b_cc] = pb.z;
            Bs[nxt][b_kq * 4 + 3][b_cc] = pb.w;
            __syncthreads();
        }
    }

    // Epilogue: L = wscale[c]*acc; accumulate exp(L - 64) per batch row.
    float ws[4];
    #pragma unroll
    for (int j = 0; j < 4; j++) {
        int c = cBase + tx * 4 + j;
        ws[j] = (c < CC) ? g_wscale[c] : 0.0f;
    }
    #pragma unroll
    for (int i = 0; i < 8; i++) {
        float s = 0.0f;
        #pragma unroll
        for (int j = 0; j < 4; j++) {
            int c = cBase + tx * 4 + j;
            if (c < CC) s += __expf(fmaf(ws[j], acc[i][j], -SCALE));
        }
        // reduce over the 16 tx lanes (lanes 0-15 / 16-31 are separate ty's)
        s += __shfl_xor_sync(0xffffffffu, s, 1);
        s += __shfl_xor_sync(0xffffffffu, s, 2);
        s += __shfl_xor_sync(0xffffffffu, s, 4);
        s += __shfl_xor_sync(0xffffffffu, s, 8);
        if (tx == 0) atomicAdd(&g_expsum[mBase + ty * 8 + i], s);
    }
}

// ---------------- per-row nll: needs label logit ----------------------------
__global__ void k_nll(const float* __restrict__ w, const void* __restrict__ labv)
{
    const int warp = threadIdx.x >> 5;
    const int lane = threadIdx.x & 31;
    const int i = blockIdx.x * 8 + warp;       // 64 blocks x 8 warps = 512 rows
    long long yi;
    if (g_is64) yi = ((const long long*)labv)[i];
    else        yi = (long long)((const int*)labv)[i];
    const float4* a4 = (const float4*)(g_xn + i * DD);
    const float4* w4 = (const float4*)(w + (size_t)yi * DD);
    float dot = 0.0f;
    #pragma unroll
    for (int q = 0; q < 4; q++) {
        float4 a = a4[q * 32 + lane];
        float4 b = w4[q * 32 + lane];
        dot += a.x * b.x + a.y * b.y + a.z * b.z + a.w * b.w;
    }
    #pragma unroll
    for (int o = 16; o > 0; o >>= 1) dot += __shfl_xor_sync(0xffffffffu, dot, o);
    if (lane == 0)
        g_nll[i] = SCALE + logf(g_expsum[i]) - g_wscale[yi] * dot;
}

// ---------------- deterministic final reduce --------------------------------
__global__ void k_reduce(float* __restrict__ out)
{
    __shared__ float sm[16];
    const int t = threadIdx.x;                 // 512 threads
    float v = g_nll[t];
    #pragma unroll
    for (int o = 16; o > 0; o >>= 1) v += __shfl_xor_sync(0xffffffffu, v, o);
    if ((t & 31) == 0) sm[t >> 5] = v;
    __syncthreads();
    if (t < 16) {
        float u = sm[t];
        #pragma unroll
        for (int o = 8; o > 0; o >>= 1) u += __shfl_xor_sync(0x0000ffffu, u, o);
        if (t == 0) out[0] = u * (1.0f / (float)BB);
    }
}

// ---------------- launch -----------------------------------------------------
extern "C" void kernel_launch(void* const* d_in, const int* in_sizes, int n_in,
                              void* d_out, int out_size)
{
    (void)out_size;
    const float* x = nullptr;
    const float* w = nullptr;
    const void* lab = nullptr;
    for (int i = 0; i < n_in; i++) {
        if (in_sizes[i] == BB * DD)      x = (const float*)d_in[i];
        else if (in_sizes[i] == CC * DD) w = (const float*)d_in[i];
        else if (in_sizes[i] == BB)      lab = d_in[i];
        // size-1 "batch" scalar: ignored
    }

    k_probe<<<1, 256>>>((const int*)lab);
    k_norm_x<<<BB, 128>>>(x);
    k_norm_w<<<CC / 8, 256>>>(w);
    dim3 g3((CC + NBT - 1) / NBT, BB / MBT);   // (1563, 4)
    k_gemm<<<g3, 256>>>(w);
    k_nll<<<BB / 8, 256>>>(w, lab);
    k_reduce<<<1, BB>>>((float*)d_out);
}

// round 8
// speedup vs baseline: 5.2320x; 5.2320x over previous
#include <cuda_runtime.h>
#include <cuda_bf16.h>
#include <math.h>
#include <stdint.h>

#define BB 512
#define DD 512
#define CC 100000
#define SCALE 64.0f

#define MBT 128          // batch tile
#define NBT 128          // class tile
#define KC  64           // K chunk (128 bytes bf16)
#define NCH (DD / KC)    // 8 chunks

// ---------------- device scratch ----------------
__device__ float          g_xn[BB * DD];          // normalized x fp32 (exact label logit)
__device__ __nv_bfloat16  g_xbf[BB * DD];         // normalized x bf16
__device__ __nv_bfloat16  g_wbf[(size_t)CC * DD]; // W * (64/||w||) bf16
__device__ float          g_wscale[CC];
__device__ float          g_expsum[BB];
__device__ float          g_nll[BB];
__device__ int            g_is64;

// ---------------- PTX helpers (baseline compute_103-safe only) --------------
__device__ __forceinline__ uint32_t smem_u32(const void* p) {
    uint32_t a;
    asm("{ .reg .u64 t; cvta.to.shared.u64 t, %1; cvt.u32.u64 %0, t; }" : "=r"(a) : "l"(p));
    return a;
}
#define CP_ASYNC16(dst, src) \
    asm volatile("cp.async.cg.shared.global [%0], [%1], 16;" :: "r"(dst), "l"(src) : "memory")
#define CP_COMMIT() asm volatile("cp.async.commit_group;" ::: "memory")
#define CP_WAIT(n)  asm volatile("cp.async.wait_group %0;" :: "n"(n) : "memory")

#define LDSM4(r, addr) \
    asm volatile("ldmatrix.sync.aligned.m8n8.x4.shared.b16 {%0,%1,%2,%3}, [%4];" \
        : "=r"((r)[0]), "=r"((r)[1]), "=r"((r)[2]), "=r"((r)[3]) : "r"(addr))

#define MMA16816(d, a, b0v, b1v) \
    asm volatile("mma.sync.aligned.m16n8k16.row.col.f32.bf16.bf16.f32 " \
        "{%0,%1,%2,%3}, {%4,%5,%6,%7}, {%8,%9}, {%0,%1,%2,%3};" \
        : "+f"((d)[0]), "+f"((d)[1]), "+f"((d)[2]), "+f"((d)[3]) \
        : "r"((a)[0]), "r"((a)[1]), "r"((a)[2]), "r"((a)[3]), "r"(b0v), "r"(b1v))

// ---------------- label dtype probe ----------------
__global__ void k_probe(const int* __restrict__ lab) {
    __shared__ int s_any;
    if (threadIdx.x == 0) s_any = 0;
    __syncthreads();
    if (lab[2 * threadIdx.x + 1] != 0) atomicOr(&s_any, 1);
    __syncthreads();
    if (threadIdx.x == 0) g_is64 = (s_any == 0) ? 1 : 0;
}

// ---------------- x normalize: fp32 + bf16 outputs, zero expsum -------------
__global__ void k_norm_x(const float* __restrict__ x) {
    __shared__ float s_part[4];
    __shared__ float s_inv;
    const int m = blockIdx.x;
    const int t = threadIdx.x;                 // 128 threads
    float4 v = ((const float4*)x)[m * 128 + t];
    float ss = v.x * v.x + v.y * v.y + v.z * v.z + v.w * v.w;
    #pragma unroll
    for (int o = 16; o > 0; o >>= 1) ss += __shfl_xor_sync(0xffffffffu, ss, o);
    if ((t & 31) == 0) s_part[t >> 5] = ss;
    __syncthreads();
    if (t == 0) {
        float tot = s_part[0] + s_part[1] + s_part[2] + s_part[3];
        s_inv = 1.0f / fmaxf(sqrtf(tot), 1e-12f);
        g_expsum[m] = 0.0f;                    // re-zeroed every graph replay
    }
    __syncthreads();
    const float inv = s_inv;
    float4 o4 = make_float4(v.x * inv, v.y * inv, v.z * inv, v.w * inv);
    ((float4*)g_xn)[m * 128 + t] = o4;
    __nv_bfloat162 h0 = __floats2bfloat162_rn(o4.x, o4.y);
    __nv_bfloat162 h1 = __floats2bfloat162_rn(o4.z, o4.w);
    uint2 u;
    u.x = *(uint32_t*)&h0; u.y = *(uint32_t*)&h1;
    *(uint2*)(g_xbf + m * DD + t * 4) = u;
}

// ---------------- W norms + scaled bf16 convert (one warp per row) ----------
__global__ void k_norm_w(const float* __restrict__ w) {
    const int c = blockIdx.x * 8 + (threadIdx.x >> 5);
    const int lane = threadIdx.x & 31;
    const float4* w4 = (const float4*)(w + (size_t)c * DD);
    float4 v[4];
    float ss = 0.0f;
    #pragma unroll
    for (int q = 0; q < 4; q++) {
        v[q] = w4[q * 32 + lane];
        ss += v[q].x * v[q].x + v[q].y * v[q].y + v[q].z * v[q].z + v[q].w * v[q].w;
    }
    #pragma unroll
    for (int o = 16; o > 0; o >>= 1) ss += __shfl_xor_sync(0xffffffffu, ss, o);
    const float sc = SCALE / fmaxf(sqrtf(ss), 1e-12f);
    if (lane == 0) g_wscale[c] = sc;
    __nv_bfloat16* dst = g_wbf + (size_t)c * DD;
    #pragma unroll
    for (int q = 0; q < 4; q++) {
        __nv_bfloat162 h0 = __floats2bfloat162_rn(v[q].x * sc, v[q].y * sc);
        __nv_bfloat162 h1 = __floats2bfloat162_rn(v[q].z * sc, v[q].w * sc);
        uint2 u;
        u.x = *(uint32_t*)&h0; u.y = *(uint32_t*)&h1;
        *(uint2*)(dst + q * 128 + lane * 4) = u;
    }
}

// ---------------- bf16 mma.sync GEMM + fused exp/sum epilogue ---------------
// Tile 128x128, K=512, 8 chunks of 64 double-buffered via cp.async.
// 8 warps (2 m x 4 n), warp tile 64x32, m16n8k16 fragments via ldmatrix.
// SMEM: A[2][128][64] bf16 (32KB) + B[2][128][64] bf16 (32KB) = 64KB dynamic.
#define SMEM_BYTES 65536

__global__ __launch_bounds__(256) void k_gemm() {
    extern __shared__ char smem[];
    __shared__ float red[MBT];
    const uint32_t sA = smem_u32(smem);          // A buffers at [0, 32KB)
    const uint32_t sB = sA + 32768;              // B buffers at [32KB, 64KB)

    const int tid  = threadIdx.x;
    const int lane = tid & 31;
    const int wid  = tid >> 5;
    const int wm   = wid >> 2;                   // 0..1
    const int wn   = wid & 3;                    // 0..3
    const int mBase = blockIdx.x * MBT;
    const int cBase = blockIdx.y * NBT;

    // ---- staging precompute: 1024 16B segs per operand per chunk ----
    uint32_t st_a[4], st_b[4];
    const __nv_bfloat16* gp_a[4];
    const __nv_bfloat16* gp_b[4];
    #pragma unroll
    for (int s = 0; s < 4; s++) {
        int lin = tid + s * 256;
        int row = lin >> 3;
        int c   = lin & 7;
        uint32_t off = (uint32_t)(row * 128 + ((c ^ (row & 7)) << 4));
        st_a[s] = sA + off;
        st_b[s] = sB + off;
        gp_a[s] = g_xbf + (size_t)(mBase + row) * DD + c * 8;
        int br = cBase + row; if (br >= CC) br = CC - 1;   // clamp; masked in epilogue
        gp_b[s] = g_wbf + (size_t)br * DD + c * 8;
    }

    // ---- ldmatrix per-lane address precompute ----
    // A frag (a0..a3): lanes 0-7 -> (m 0-7, k0-7), 8-15 -> (m 8-15, k0-7),
    //                  16-23 -> (m 0-7, k8-15), 24-31 -> (m 8-15, k8-15)
    const int arow = (lane & 7) + 8 * ((lane >> 3) & 1);
    const int akh  = lane >> 4;
    // B frag (b0,b1 / b0',b1'): lanes 0-7 -> (n 0-7, k0-7), 8-15 -> (n 0-7, k8-15),
    //                           16-23 -> (n 8-15, k0-7), 24-31 -> (n 8-15, k8-15)
    const int brow = (lane & 7) + 8 * (lane >> 4);
    const int bkh  = (lane >> 3) & 1;
    const int swz  = lane & 7;
    uint32_t aptr[4], bptr[2];
    #pragma unroll
    for (int mi = 0; mi < 4; mi++)
        aptr[mi] = sA + (uint32_t)((wm * 64 + mi * 16 + arow) * 128);
    #pragma unroll
    for (int jp = 0; jp < 2; jp++)
        bptr[jp] = sB + (uint32_t)((wn * 32 + jp * 16 + brow) * 128);

    float d[4][4][4];
    #pragma unroll
    for (int mi = 0; mi < 4; mi++)
        #pragma unroll
        for (int nj = 0; nj < 4; nj++)
            #pragma unroll
            for (int r = 0; r < 4; r++) d[mi][nj][r] = 0.0f;

    // ---- prologue: stage chunk 0 into buf 0 ----
    #pragma unroll
    for (int s = 0; s < 4; s++) {
        CP_ASYNC16(st_a[s], gp_a[s]);
        CP_ASYNC16(st_b[s], gp_b[s]);
    }
    CP_COMMIT();

    for (int kc = 0; kc < NCH; kc++) {
        const uint32_t bufoff = (uint32_t)((kc & 1) * 16384);
        if (kc + 1 < NCH) {
            const uint32_t nb = (uint32_t)(((kc + 1) & 1) * 16384);
            #pragma unroll
            for (int s = 0; s < 4; s++) {
                CP_ASYNC16(st_a[s] + nb, gp_a[s] + (kc + 1) * KC);
                CP_ASYNC16(st_b[s] + nb, gp_b[s] + (kc + 1) * KC);
            }
            CP_COMMIT();
            CP_WAIT(1);                 // chunk kc has landed
        } else {
            CP_WAIT(0);
        }
        __syncthreads();

        #pragma unroll
        for (int ks = 0; ks < 4; ks++) {
            const uint32_t cA = (uint32_t)(((ks * 2 + akh) ^ swz) << 4);
            const uint32_t cB = (uint32_t)(((ks * 2 + bkh) ^ swz) << 4);
            uint32_t a[4][4], b[2][4];
            #pragma unroll
            for (int mi = 0; mi < 4; mi++) LDSM4(a[mi], aptr[mi] + bufoff + cA);
            #pragma unroll
            for (int jp = 0; jp < 2; jp++) LDSM4(b[jp], bptr[jp] + bufoff + cB);
            #pragma unroll
            for (int mi = 0; mi < 4; mi++) {
                MMA16816(d[mi][0], a[mi], b[0][0], b[0][1]);
                MMA16816(d[mi][1], a[mi], b[0][2], b[0][3]);
                MMA16816(d[mi][2], a[mi], b[1][0], b[1][1]);
                MMA16816(d[mi][3], a[mi], b[1][2], b[1][3]);
            }
        }
        __syncthreads();                // buffer safe to overwrite next iter
    }

    // ---- epilogue: logits are d[] directly (scale folded into g_wbf) ----
    if (tid < MBT) red[tid] = 0.0f;
    __syncthreads();

    const int q  = lane & 3;
    const int g4 = lane >> 2;
    #pragma unroll
    for (int mi = 0; mi < 4; mi++) {
        float r0 = 0.0f, r1 = 0.0f;
        #pragma unroll
        for (int nj = 0; nj < 4; nj++) {
            int c0 = cBase + wn * 32 + nj * 8 + q * 2;
            if (c0 < CC)     { r0 += __expf(d[mi][nj][0] - SCALE);
                               r1 += __expf(d[mi][nj][2] - SCALE); }
            if (c0 + 1 < CC) { r0 += __expf(d[mi][nj][1] - SCALE);
                               r1 += __expf(d[mi][nj][3] - SCALE); }
        }
        r0 += __shfl_xor_sync(0xffffffffu, r0, 1);
        r0 += __shfl_xor_sync(0xffffffffu, r0, 2);
        r1 += __shfl_xor_sync(0xffffffffu, r1, 1);
        r1 += __shfl_xor_sync(0xffffffffu, r1, 2);
        if (q == 0) {
            atomicAdd(&red[wm * 64 + mi * 16 + g4],     r0);
            atomicAdd(&red[wm * 64 + mi * 16 + 8 + g4], r1);
        }
    }
    __syncthreads();
    if (tid < MBT) atomicAdd(&g_expsum[mBase + tid], red[tid]);
}

// ---------------- per-row nll (exact fp32 label logit) ----------------------
__global__ void k_nll(const float* __restrict__ w, const void* __restrict__ labv) {
    const int warp = threadIdx.x >> 5;
    const int lane = threadIdx.x & 31;
    const int i = blockIdx.x * 8 + warp;
    long long yi;
    if (g_is64) yi = ((const long long*)labv)[i];
    else        yi = (long long)((const int*)labv)[i];
    const float4* a4 = (const float4*)(g_xn + i * DD);
    const float4* w4 = (const float4*)(w + (size_t)yi * DD);
    float dot = 0.0f;
    #pragma unroll
    for (int qq = 0; qq < 4; qq++) {
        float4 a = a4[qq * 32 + lane];
        float4 b = w4[qq * 32 + lane];
        dot += a.x * b.x + a.y * b.y + a.z * b.z + a.w * b.w;
    }
    #pragma unroll
    for (int o = 16; o > 0; o >>= 1) dot += __shfl_xor_sync(0xffffffffu, dot, o);
    if (lane == 0)
        g_nll[i] = SCALE + logf(g_expsum[i]) - g_wscale[yi] * dot;
}

// ---------------- deterministic final reduce --------------------------------
__global__ void k_reduce(float* __restrict__ out) {
    __shared__ float sm[16];
    const int t = threadIdx.x;
    float v = g_nll[t];
    #pragma unroll
    for (int o = 16; o > 0; o >>= 1) v += __shfl_xor_sync(0xffffffffu, v, o);
    if ((t & 31) == 0) sm[t >> 5] = v;
    __syncthreads();
    if (t < 16) {
        float u = sm[t];
        #pragma unroll
        for (int o = 8; o > 0; o >>= 1) u += __shfl_xor_sync(0x0000ffffu, u, o);
        if (t == 0) out[0] = u * (1.0f / (float)BB);
    }
}

// ---------------- launch -----------------------------------------------------
extern "C" void kernel_launch(void* const* d_in, const int* in_sizes, int n_in,
                              void* d_out, int out_size) {
    (void)out_size;
    const float* x = nullptr;
    const float* w = nullptr;
    const void* lab = nullptr;
    for (int i = 0; i < n_in; i++) {
        if (in_sizes[i] == BB * DD)      x = (const float*)d_in[i];
        else if (in_sizes[i] == CC * DD) w = (const float*)d_in[i];
        else if (in_sizes[i] == BB)      lab = d_in[i];
    }

    cudaFuncSetAttribute(k_gemm, cudaFuncAttributeMaxDynamicSharedMemorySize, SMEM_BYTES);

    k_probe<<<1, 256>>>((const int*)lab);
    k_norm_x<<<BB, 128>>>(x);
    k_norm_w<<<CC / 8, 256>>>(w);
    dim3 g3(BB / MBT, (CC + NBT - 1) / NBT);   // (4, 782): batch-fast for L2 W reuse
    k_gemm<<<g3, 256, SMEM_BYTES>>>();
    k_nll<<<BB / 8, 256>>>(w, lab);
    k_reduce<<<1, BB>>>((float*)d_out);
}